// round 1
// baseline (speedup 1.0000x reference)
#include <cuda_runtime.h>
#include <math_constants.h>

// ---------------------------------------------------------------------------
// Problem constants
// ---------------------------------------------------------------------------
#define B_  2
#define S_  2048
#define D_  768
#define F_  3072
#define H_  12
#define HD_ 64
#define M_  (B_ * S_)   // 4096 rows

// ---------------------------------------------------------------------------
// Scratch (static device allocations are the allowed mechanism)
// ---------------------------------------------------------------------------
__device__ float g_Q[M_ * D_];
__device__ float g_K[M_ * D_];
__device__ float g_V[M_ * D_];
__device__ float g_attn[M_ * D_];
__device__ float g_t1[M_ * D_];
__device__ float g_x1[M_ * D_];
__device__ float g_ff[(size_t)M_ * F_];
__device__ float g_t2[M_ * D_];

// ---------------------------------------------------------------------------
// Generic fp32 GEMM: C[M,N] = A[M,K] @ W[K,N] + bias (+ resid) (+ReLU)
// 64x64x16 tile, 256 threads, 4x4 per-thread register tile.
// A stored transposed in smem; all smem reads are float4 (conflict-free).
// Requires M%64==0, N%64==0, K%16==0 (true for all shapes here).
// ---------------------------------------------------------------------------
template <bool RELU>
__global__ __launch_bounds__(256)
void gemm_kernel(const float* __restrict__ A, const float* __restrict__ W,
                 const float* __restrict__ bias, const float* __restrict__ resid,
                 float* __restrict__ C, int M, int N, int K)
{
    __shared__ float As[16][68];   // [k][m]
    __shared__ float Bs[16][68];   // [k][n]

    const int tid = threadIdx.x;
    const int tx = tid & 15;         // 0..15 -> N direction
    const int ty = tid >> 4;         // 0..15 -> M direction
    const int bm = blockIdx.y * 64;
    const int bn = blockIdx.x * 64;

    // load indices
    const int ar = tid >> 2;            // 0..63 (row in A tile)
    const int ac = (tid & 3) << 2;      // 0,4,8,12 (k offset)
    const int wr = tid >> 4;            // 0..15 (k row in W tile)
    const int wc = (tid & 15) << 2;     // 0..60 (n offset)

    const float* Aptr = A + (size_t)(bm + ar) * K + ac;
    const float* Wptr = W + (size_t)wr * N + bn + wc;

    float acc[4][4] = {};

    for (int kt = 0; kt < K; kt += 16) {
        float4 a4 = *(const float4*)(Aptr + kt);
        float4 w4 = *(const float4*)(Wptr + (size_t)kt * N);
        As[ac + 0][ar] = a4.x;
        As[ac + 1][ar] = a4.y;
        As[ac + 2][ar] = a4.z;
        As[ac + 3][ar] = a4.w;
        *(float4*)&Bs[wr][wc] = w4;
        __syncthreads();

        #pragma unroll
        for (int kk = 0; kk < 16; kk++) {
            float4 a = *(const float4*)&As[kk][ty << 2];
            float4 b = *(const float4*)&Bs[kk][tx << 2];
            acc[0][0] += a.x * b.x; acc[0][1] += a.x * b.y;
            acc[0][2] += a.x * b.z; acc[0][3] += a.x * b.w;
            acc[1][0] += a.y * b.x; acc[1][1] += a.y * b.y;
            acc[1][2] += a.y * b.z; acc[1][3] += a.y * b.w;
            acc[2][0] += a.z * b.x; acc[2][1] += a.z * b.y;
            acc[2][2] += a.z * b.z; acc[2][3] += a.z * b.w;
            acc[3][0] += a.w * b.x; acc[3][1] += a.w * b.y;
            acc[3][2] += a.w * b.z; acc[3][3] += a.w * b.w;
        }
        __syncthreads();
    }

    const int cn = bn + (tx << 2);
    float4 bv = *(const float4*)(bias + cn);
    #pragma unroll
    for (int i = 0; i < 4; i++) {
        size_t row = (size_t)(bm + (ty << 2) + i);
        float4 o;
        o.x = acc[i][0] + bv.x;
        o.y = acc[i][1] + bv.y;
        o.z = acc[i][2] + bv.z;
        o.w = acc[i][3] + bv.w;
        if (resid != nullptr) {
            float4 r = *(const float4*)(resid + row * N + cn);
            o.x += r.x; o.y += r.y; o.z += r.z; o.w += r.w;
        }
        if (RELU) {
            o.x = fmaxf(o.x, 0.f); o.y = fmaxf(o.y, 0.f);
            o.z = fmaxf(o.z, 0.f); o.w = fmaxf(o.w, 0.f);
        }
        *(float4*)(C + row * N + cn) = o;
    }
}

// ---------------------------------------------------------------------------
// Flash attention (fp32, online softmax). Q/K/V are [B,S,D] row-major with
// head h occupying columns [h*64, h*64+64). One CTA = 64 query rows of one
// (b,h); iterates over 32 key tiles of 64.
// Dynamic smem: Qt[64d][68] + KV[64][68] + Pt[64key][68] = 52224 bytes.
// ---------------------------------------------------------------------------
__global__ __launch_bounds__(256)
void attn_kernel(const float* __restrict__ Q, const float* __restrict__ K,
                 const float* __restrict__ V, float* __restrict__ O)
{
    extern __shared__ float sm[];
    float* Qt = sm;              // [d][row]
    float* KV = sm + 64 * 68;    // K phase: [d][key]; V phase: [key][d]
    float* Pt = sm + 2 * 64 * 68;// [key][row]

    const int tid = threadIdx.x;
    const int tx = tid & 15;     // key / dim direction
    const int ty = tid >> 4;     // query-row direction
    const int bh = blockIdx.y;
    const int b = bh / H_;
    const int h = bh % H_;
    const int q0 = blockIdx.x * 64;
    const size_t hb = (size_t)b * S_ * D_ + (size_t)h * HD_;

    const int lr = tid >> 2;          // row within 64-row tile
    const int ld = (tid & 3) << 4;    // 16 consecutive dims per thread

    // Load Q tile transposed, folding the 1/sqrt(64) scale into Q.
    {
        const float* src = Q + hb + (size_t)(q0 + lr) * D_ + ld;
        #pragma unroll
        for (int i = 0; i < 4; i++) {
            float4 v = *(const float4*)(src + i * 4);
            int d = ld + i * 4;
            Qt[(d + 0) * 68 + lr] = v.x * 0.125f;
            Qt[(d + 1) * 68 + lr] = v.y * 0.125f;
            Qt[(d + 2) * 68 + lr] = v.z * 0.125f;
            Qt[(d + 3) * 68 + lr] = v.w * 0.125f;
        }
    }

    float m_i[4], l_i[4], acc[4][4];
    #pragma unroll
    for (int i = 0; i < 4; i++) {
        m_i[i] = -CUDART_INF_F;
        l_i[i] = 0.f;
        #pragma unroll
        for (int j = 0; j < 4; j++) acc[i][j] = 0.f;
    }

    for (int kt = 0; kt < S_; kt += 64) {
        // Load K tile transposed: KV[d][key]
        {
            const float* src = K + hb + (size_t)(kt + lr) * D_ + ld;
            #pragma unroll
            for (int i = 0; i < 4; i++) {
                float4 v = *(const float4*)(src + i * 4);
                int d = ld + i * 4;
                KV[(d + 0) * 68 + lr] = v.x;
                KV[(d + 1) * 68 + lr] = v.y;
                KV[(d + 2) * 68 + lr] = v.z;
                KV[(d + 3) * 68 + lr] = v.w;
            }
        }
        __syncthreads();

        // Scores: sf[i][j] = (Q/8) . K  over 64 dims
        float sf[4][4] = {};
        #pragma unroll 16
        for (int d = 0; d < 64; d++) {
            float4 a = *(const float4*)&Qt[d * 68 + (ty << 2)];
            float4 bb = *(const float4*)&KV[d * 68 + (tx << 2)];
            sf[0][0] += a.x * bb.x; sf[0][1] += a.x * bb.y;
            sf[0][2] += a.x * bb.z; sf[0][3] += a.x * bb.w;
            sf[1][0] += a.y * bb.x; sf[1][1] += a.y * bb.y;
            sf[1][2] += a.y * bb.z; sf[1][3] += a.y * bb.w;
            sf[2][0] += a.z * bb.x; sf[2][1] += a.z * bb.y;
            sf[2][2] += a.z * bb.z; sf[2][3] += a.z * bb.w;
            sf[3][0] += a.w * bb.x; sf[3][1] += a.w * bb.y;
            sf[3][2] += a.w * bb.z; sf[3][3] += a.w * bb.w;
        }

        // Online softmax (row stats shared by the 16 tx-threads of each row)
        #pragma unroll
        for (int i = 0; i < 4; i++) {
            float mx = fmaxf(fmaxf(sf[i][0], sf[i][1]), fmaxf(sf[i][2], sf[i][3]));
            #pragma unroll
            for (int o = 8; o; o >>= 1)
                mx = fmaxf(mx, __shfl_xor_sync(0xffffffffu, mx, o));
            float mn = fmaxf(m_i[i], mx);
            float rs = 0.f;
            #pragma unroll
            for (int j = 0; j < 4; j++) {
                float p = __expf(sf[i][j] - mn);
                sf[i][j] = p;
                rs += p;
            }
            #pragma unroll
            for (int o = 8; o; o >>= 1)
                rs += __shfl_xor_sync(0xffffffffu, rs, o);
            float c = __expf(m_i[i] - mn);
            l_i[i] = l_i[i] * c + rs;
            m_i[i] = mn;
            #pragma unroll
            for (int j = 0; j < 4; j++) acc[i][j] *= c;
        }

        // Store P transposed: Pt[key][row]
        #pragma unroll
        for (int i = 0; i < 4; i++)
            #pragma unroll
            for (int j = 0; j < 4; j++)
                Pt[((tx << 2) + j) * 68 + (ty << 2) + i] = sf[i][j];
        __syncthreads();   // P written; K reads done -> KV reusable

        // Load V tile natural: KV[key][d]
        {
            const float* src = V + hb + (size_t)(kt + lr) * D_ + ld;
            #pragma unroll
            for (int i = 0; i < 4; i++)
                *(float4*)&KV[lr * 68 + ld + i * 4] = *(const float4*)(src + i * 4);
        }
        __syncthreads();

        // acc += P^T-major GEMM: acc[r][d] += P[r][k] * V[k][d]
        #pragma unroll 16
        for (int k = 0; k < 64; k++) {
            float4 a = *(const float4*)&Pt[k * 68 + (ty << 2)];
            float4 bb = *(const float4*)&KV[k * 68 + (tx << 2)];
            acc[0][0] += a.x * bb.x; acc[0][1] += a.x * bb.y;
            acc[0][2] += a.x * bb.z; acc[0][3] += a.x * bb.w;
            acc[1][0] += a.y * bb.x; acc[1][1] += a.y * bb.y;
            acc[1][2] += a.y * bb.z; acc[1][3] += a.y * bb.w;
            acc[2][0] += a.z * bb.x; acc[2][1] += a.z * bb.y;
            acc[2][2] += a.z * bb.z; acc[2][3] += a.z * bb.w;
            acc[3][0] += a.w * bb.x; acc[3][1] += a.w * bb.y;
            acc[3][2] += a.w * bb.z; acc[3][3] += a.w * bb.w;
        }
        __syncthreads();
    }

    // Write normalized output into [B,S,D] layout (head h column block)
    #pragma unroll
    for (int i = 0; i < 4; i++) {
        float inv = 1.f / l_i[i];
        float4 o = make_float4(acc[i][0] * inv, acc[i][1] * inv,
                               acc[i][2] * inv, acc[i][3] * inv);
        size_t row = (size_t)b * S_ + q0 + (ty << 2) + i;
        *(float4*)(O + row * D_ + h * HD_ + (tx << 2)) = o;
    }
}

// ---------------------------------------------------------------------------
// Row LayerNorm over D_=768 columns. One CTA per row, 256 threads x 3 elems.
// ---------------------------------------------------------------------------
__global__ __launch_bounds__(256)
void ln_kernel(const float* __restrict__ X, const float* __restrict__ g,
               const float* __restrict__ be, float* __restrict__ Y)
{
    const int row = blockIdx.x;
    const float* xr = X + (size_t)row * D_;
    float v[3];
    float s = 0.f, ss = 0.f;
    #pragma unroll
    for (int i = 0; i < 3; i++) {
        v[i] = xr[threadIdx.x + i * 256];
        s += v[i];
        ss += v[i] * v[i];
    }
    #pragma unroll
    for (int o = 16; o; o >>= 1) {
        s += __shfl_xor_sync(0xffffffffu, s, o);
        ss += __shfl_xor_sync(0xffffffffu, ss, o);
    }
    __shared__ float red[16];
    const int wid = threadIdx.x >> 5, lid = threadIdx.x & 31;
    if (lid == 0) { red[wid] = s; red[wid + 8] = ss; }
    __syncthreads();
    s = 0.f; ss = 0.f;
    #pragma unroll
    for (int w = 0; w < 8; w++) { s += red[w]; ss += red[w + 8]; }
    const float mean = s * (1.f / D_);
    const float var = ss * (1.f / D_) - mean * mean;
    const float rstd = rsqrtf(var + 1e-5f);
    #pragma unroll
    for (int i = 0; i < 3; i++) {
        int c = threadIdx.x + i * 256;
        Y[(size_t)row * D_ + c] = (v[i] - mean) * rstd * g[c] + be[c];
    }
}

// ---------------------------------------------------------------------------
// Launch
// ---------------------------------------------------------------------------
extern "C" void kernel_launch(void* const* d_in, const int* in_sizes, int n_in,
                              void* d_out, int out_size)
{
    const float* x  = (const float*)d_in[0];
    const float* Wq = (const float*)d_in[1];
    const float* bq = (const float*)d_in[2];
    const float* Wk = (const float*)d_in[3];
    const float* bk = (const float*)d_in[4];
    const float* Wv = (const float*)d_in[5];
    const float* bv = (const float*)d_in[6];
    const float* Wo = (const float*)d_in[7];
    const float* bo = (const float*)d_in[8];
    const float* W1 = (const float*)d_in[9];
    const float* b1 = (const float*)d_in[10];
    const float* W2 = (const float*)d_in[11];
    const float* b2 = (const float*)d_in[12];
    const float* g1 = (const float*)d_in[13];
    const float* be1 = (const float*)d_in[14];
    const float* g2 = (const float*)d_in[15];
    const float* be2 = (const float*)d_in[16];
    float* out = (float*)d_out;

    float *Qp, *Kp, *Vp, *attnp, *t1p, *x1p, *ffp, *t2p;
    cudaGetSymbolAddress((void**)&Qp, g_Q);
    cudaGetSymbolAddress((void**)&Kp, g_K);
    cudaGetSymbolAddress((void**)&Vp, g_V);
    cudaGetSymbolAddress((void**)&attnp, g_attn);
    cudaGetSymbolAddress((void**)&t1p, g_t1);
    cudaGetSymbolAddress((void**)&x1p, g_x1);
    cudaGetSymbolAddress((void**)&ffp, g_ff);
    cudaGetSymbolAddress((void**)&t2p, g_t2);

    const dim3 gD(D_ / 64, M_ / 64);   // 12 x 64
    const dim3 gF(F_ / 64, M_ / 64);   // 48 x 64

    // QKV projections
    gemm_kernel<false><<<gD, 256>>>(x, Wq, bq, nullptr, Qp, M_, D_, D_);
    gemm_kernel<false><<<gD, 256>>>(x, Wk, bk, nullptr, Kp, M_, D_, D_);
    gemm_kernel<false><<<gD, 256>>>(x, Wv, bv, nullptr, Vp, M_, D_, D_);

    // Attention
    const int attn_smem = 3 * 64 * 68 * (int)sizeof(float);  // 52224
    cudaFuncSetAttribute(attn_kernel, cudaFuncAttributeMaxDynamicSharedMemorySize,
                         attn_smem);
    attn_kernel<<<dim3(S_ / 64, B_ * H_), 256, attn_smem>>>(Qp, Kp, Vp, attnp);

    // O-proj + residual, LN1
    gemm_kernel<false><<<gD, 256>>>(attnp, Wo, bo, x, t1p, M_, D_, D_);
    ln_kernel<<<M_, 256>>>(t1p, g1, be1, x1p);

    // FFN
    gemm_kernel<true><<<gF, 256>>>(x1p, W1, b1, nullptr, ffp, M_, F_, D_);
    gemm_kernel<false><<<gD, 256>>>(ffp, W2, b2, x1p, t2p, M_, D_, F_);
    ln_kernel<<<M_, 256>>>(t2p, g2, be2, out);
}